// round 11
// baseline (speedup 1.0000x reference)
#include <cuda_runtime.h>
#include <cstddef>

#define NV 25000
#define NE 400000
#define H  192
#define BM 64
#define SAF 196   // A smem stride (floats); 196%32=4 -> frag LDS conflict-free
#define SB  200   // B smem stride (floats); conflict-free frag loads

// ---------------- scratch (static device globals; no runtime allocation) ---------
__device__ float g_X[(size_t)NV * H];   // intra-block activation
__device__ float g_F[(size_t)NV * H];   // feats (residual stream)
__device__ int   g_rowptr[NV + 1];
__device__ int   g_cnt[NV];
__device__ int   g_fill[NV];
__device__ int   g_ssrc[NE];
__device__ float g_sw[NE];

// ---------------- CSR build ------------------------------------------------------
__global__ void k_zero2(int* a, int* b, int n) {
    int i = blockIdx.x * blockDim.x + threadIdx.x;
    if (i < n) { a[i] = 0; b[i] = 0; }
}

__global__ void k_hist(const int* __restrict__ dst, int* cnt, int E) {
    int i = blockIdx.x * blockDim.x + threadIdx.x;
    if (i < E) atomicAdd(&cnt[dst[i]], 1);
}

__global__ void k_scan(const int* __restrict__ cnt, int* __restrict__ rowptr, int n) {
    __shared__ int sh[1024];
    __shared__ int s_carry;
    if (threadIdx.x == 0) s_carry = 0;
    __syncthreads();
    for (int base = 0; base < n; base += 1024) {
        int i = base + threadIdx.x;
        int v = (i < n) ? cnt[i] : 0;
        int x = v;
        sh[threadIdx.x] = x;
        __syncthreads();
        for (int off = 1; off < 1024; off <<= 1) {
            int t = (threadIdx.x >= off) ? sh[threadIdx.x - off] : 0;
            __syncthreads();
            x += t;
            sh[threadIdx.x] = x;
            __syncthreads();
        }
        int carry = s_carry;
        if (i < n) rowptr[i] = carry + x - v;
        __syncthreads();
        if (threadIdx.x == 1023) s_carry = carry + sh[1023];
        __syncthreads();
    }
    if (threadIdx.x == 0) rowptr[n] = s_carry;
}

__global__ void k_scatter(const int* __restrict__ src, const int* __restrict__ dst,
                          const float* __restrict__ w, const int* __restrict__ rowptr,
                          int* fill, int* ssrc, float* sw, int E) {
    int i = blockIdx.x * blockDim.x + threadIdx.x;
    if (i < E) {
        int d = dst[i];
        int pos = rowptr[d] + atomicAdd(&fill[d], 1);
        ssrc[pos] = src[i];
        sw[pos]   = w[i];
    }
}

// ---------------- tf32 helpers ---------------------------------------------------
__device__ __forceinline__ unsigned f2tf32(float x) {
    unsigned u;
    asm("cvt.rna.tf32.f32 %0, %1;" : "=r"(u) : "f"(x));
    return u;
}

__device__ __forceinline__ void mma_tf32(float* c, const unsigned* a,
                                         unsigned b0, unsigned b1) {
    asm volatile(
        "mma.sync.aligned.m16n8k8.row.col.f32.tf32.tf32.f32 "
        "{%0,%1,%2,%3}, {%4,%5,%6,%7}, {%8,%9}, {%0,%1,%2,%3};"
        : "+f"(c[0]), "+f"(c[1]), "+f"(c[2]), "+f"(c[3])
        : "r"(a[0]), "r"(a[1]), "r"(a[2]), "r"(a[3]), "r"(b0), "r"(b1));
}

// ---------------- fused layer: out = eps(relu(agg(X) @ W + b)) -------------------
// mode 0: out = relu(.)            mode 1: out = (res + relu(.)) * 0.5
// out2 (optional, mode 1): second destination written with same values.
// block: 64 dst rows, 256 threads.
// phase 1: warp w gathers rows w*8..w*8+7 into smem as tf32 bits.
// phase 2: tf32 MMA, warp tile 32x48, K staged from Wm in 32-chunks.
extern __shared__ float s_dyn[];

__global__ __launch_bounds__(256) void k_fused(const float* __restrict__ X,
                                               const int* __restrict__ rowptr,
                                               const int* __restrict__ ssrc,
                                               const float* __restrict__ sw,
                                               const float* __restrict__ Wm,
                                               const float* __restrict__ bias,
                                               const float* __restrict__ res,
                                               float* __restrict__ out,
                                               float* __restrict__ out2,
                                               int M, int mode) {
    unsigned* Ys = (unsigned*)s_dyn;            // 64 x SAF (tf32 bits)
    unsigned* Bs = (unsigned*)(s_dyn + BM * SAF); // 32 x SB  (tf32 bits)

    int tid  = threadIdx.x;
    int lane = tid & 31;
    int warp = tid >> 5;
    int m0   = blockIdx.x * BM;

    // ---- phase 1: aggregate 8 rows per warp into smem ----
#pragma unroll 1
    for (int i = 0; i < 8; i++) {
        int row = warp * 8 + i;
        int d   = m0 + row;
        float4 a4 = make_float4(0.f, 0.f, 0.f, 0.f);
        float2 a2 = make_float2(0.f, 0.f);
        if (d < M) {
            int beg = rowptr[d], end = rowptr[d + 1];
#pragma unroll 2
            for (int e = beg; e < end; e++) {
                int   s  = __ldg(ssrc + e);
                float wt = __ldg(sw + e);
                const float* r = X + (size_t)s * H;
                float4 v4 = __ldg((const float4*)r + lane);
                float2 v2 = __ldg((const float2*)(r + 128) + lane);
                a4.x += wt * v4.x;
                a4.y += wt * v4.y;
                a4.z += wt * v4.z;
                a4.w += wt * v4.w;
                a2.x += wt * v2.x;
                a2.y += wt * v2.y;
            }
        }
        unsigned* o = Ys + row * SAF;
        o[lane * 4 + 0] = f2tf32(a4.x);
        o[lane * 4 + 1] = f2tf32(a4.y);
        o[lane * 4 + 2] = f2tf32(a4.z);
        o[lane * 4 + 3] = f2tf32(a4.w);
        o[128 + lane * 2 + 0] = f2tf32(a2.x);
        o[128 + lane * 2 + 1] = f2tf32(a2.y);
    }

    // ---- phase 2: GEMM from smem A ----
    int gid  = lane >> 2;    // 0..7
    int tig  = lane & 3;     // 0..3
    int rowg = warp & 1;     // warp row group (32 rows)
    int colg = warp >> 1;    // warp col group (48 cols)

    float c[2][6][4];
#pragma unroll
    for (int t = 0; t < 2; t++)
#pragma unroll
        for (int j = 0; j < 6; j++)
#pragma unroll
            for (int q = 0; q < 4; q++) c[t][j][q] = 0.f;

    for (int it = 0; it < 6; it++) {
        int k0 = it * 32;
        __syncthreads();   // phase-1 done (it==0) / previous compute done
        // stage B chunk 32x192: 6 float4 per thread
#pragma unroll
        for (int i = 0; i < 6; i++) {
            int f4  = tid + 256 * i;
            int row = f4 / 48;
            int cc  = (f4 % 48) * 4;
            float4 w = *(const float4*)(Wm + (size_t)(k0 + row) * H + cc);
            unsigned* d = &Bs[row * SB + cc];
            d[0] = f2tf32(w.x); d[1] = f2tf32(w.y);
            d[2] = f2tf32(w.z); d[3] = f2tf32(w.w);
        }
        __syncthreads();
#pragma unroll
        for (int ks = 0; ks < 4; ks++) {
            int kk = k0 + ks * 8;
            unsigned a[2][4];
#pragma unroll
            for (int t = 0; t < 2; t++) {
                int r = rowg * 32 + t * 16 + gid;
                a[t][0] = Ys[r * SAF + kk + tig];
                a[t][1] = Ys[(r + 8) * SAF + kk + tig];
                a[t][2] = Ys[r * SAF + kk + tig + 4];
                a[t][3] = Ys[(r + 8) * SAF + kk + tig + 4];
            }
#pragma unroll
            for (int j = 0; j < 6; j++) {
                int n = colg * 48 + j * 8 + gid;
                unsigned b0 = Bs[(ks * 8 + tig) * SB + n];
                unsigned b1 = Bs[(ks * 8 + tig + 4) * SB + n];
                mma_tf32(c[0][j], a[0], b0, b1);
                mma_tf32(c[1][j], a[1], b0, b1);
            }
        }
    }

    // ---- epilogue ----
    float2 bb[6];
#pragma unroll
    for (int j = 0; j < 6; j++)
        bb[j] = *(const float2*)(bias + colg * 48 + j * 8 + tig * 2);

#pragma unroll
    for (int t = 0; t < 2; t++) {
#pragma unroll
        for (int h = 0; h < 2; h++) {
            int m = m0 + rowg * 32 + t * 16 + gid + h * 8;
            if (m < M) {
                size_t off = (size_t)m * H + colg * 48 + tig * 2;
                float* orow = out + off;
                const float* rrow = res + off;
#pragma unroll
                for (int j = 0; j < 6; j++) {
                    float v0 = fmaxf(c[t][j][h * 2 + 0] + bb[j].x, 0.f);
                    float v1 = fmaxf(c[t][j][h * 2 + 1] + bb[j].y, 0.f);
                    if (mode == 1) {
                        float2 r2 = *(const float2*)(rrow + j * 8);
                        v0 = (r2.x + v0) * 0.5f;
                        v1 = (r2.y + v1) * 0.5f;
                    }
                    float2 o2; o2.x = v0; o2.y = v1;
                    *(float2*)(orow + j * 8) = o2;
                    if (out2) *(float2*)(out2 + off + j * 8) = o2;
                }
            }
        }
    }
}

// ---------------- fused output head: coords = agg(F) @ W_out + b_out -------------
// one warp per dst; lane covers cols {lane*4..+3, 128+lane*2..+1}; warp-reduce 3 dots.
__global__ __launch_bounds__(256) void k_agg_head(const float* __restrict__ X,
                                                  const int* __restrict__ rowptr,
                                                  const int* __restrict__ ssrc,
                                                  const float* __restrict__ sw,
                                                  const float* __restrict__ Wout,
                                                  const float* __restrict__ bout,
                                                  float* __restrict__ out, int M) {
    int warp = (blockIdx.x * blockDim.x + threadIdx.x) >> 5;
    int lane = threadIdx.x & 31;
    if (warp >= M) return;
    int beg = rowptr[warp], end = rowptr[warp + 1];
    float4 a4 = make_float4(0.f, 0.f, 0.f, 0.f);
    float2 a2 = make_float2(0.f, 0.f);
#pragma unroll 2
    for (int e = beg; e < end; e++) {
        int   s  = __ldg(ssrc + e);
        float wt = __ldg(sw + e);
        const float* r = X + (size_t)s * H;
        float4 v4 = __ldg((const float4*)r + lane);
        float2 v2 = __ldg((const float2*)(r + 128) + lane);
        a4.x += wt * v4.x;
        a4.y += wt * v4.y;
        a4.z += wt * v4.z;
        a4.w += wt * v4.w;
        a2.x += wt * v2.x;
        a2.y += wt * v2.y;
    }
    // dot with W_out columns; this lane's cols:
    int c0 = lane * 4;          // 4 cols
    int c1 = 128 + lane * 2;    // 2 cols
    float s0 = 0.f, s1 = 0.f, s2 = 0.f;
    float av[6] = {a4.x, a4.y, a4.z, a4.w, a2.x, a2.y};
    int   cv[6] = {c0, c0 + 1, c0 + 2, c0 + 3, c1, c1 + 1};
#pragma unroll
    for (int q = 0; q < 6; q++) {
        const float* wr = Wout + (size_t)cv[q] * 3;
        s0 += av[q] * __ldg(wr + 0);
        s1 += av[q] * __ldg(wr + 1);
        s2 += av[q] * __ldg(wr + 2);
    }
#pragma unroll
    for (int off = 16; off; off >>= 1) {
        s0 += __shfl_down_sync(0xffffffffu, s0, off);
        s1 += __shfl_down_sync(0xffffffffu, s1, off);
        s2 += __shfl_down_sync(0xffffffffu, s2, off);
    }
    if (lane == 0) {
        out[(size_t)warp * 3 + 0] = s0 + __ldg(bout + 0);
        out[(size_t)warp * 3 + 1] = s1 + __ldg(bout + 1);
        out[(size_t)warp * 3 + 2] = s2 + __ldg(bout + 2);
    }
}

// ---------------- launch ---------------------------------------------------------
#define SMEM_FUSED ((BM * SAF + 32 * SB) * 4)   // 75776 bytes

extern "C" void kernel_launch(void* const* d_in, const int* in_sizes, int n_in,
                              void* d_out, int out_size) {
    const float* features = (const float*)d_in[0];
    const int*   esrc     = (const int*)d_in[1];
    const int*   edst     = (const int*)d_in[2];
    const float* ew       = (const float*)d_in[3];
    const float* Ws       = (const float*)d_in[4];
    const float* bs       = (const float*)d_in[5];
    const float* Wout     = (const float*)d_in[6];
    const float* bout     = (const float*)d_in[7];
    float* out = (float*)d_out;

    int M = in_sizes[0] / H;   // 25000
    int E = in_sizes[1];       // 400000

    float *X, *F, *sw;
    int *rp, *cnt, *fill, *ssrc;
    cudaGetSymbolAddress((void**)&X, g_X);
    cudaGetSymbolAddress((void**)&F, g_F);
    cudaGetSymbolAddress((void**)&sw, g_sw);
    cudaGetSymbolAddress((void**)&rp, g_rowptr);
    cudaGetSymbolAddress((void**)&cnt, g_cnt);
    cudaGetSymbolAddress((void**)&fill, g_fill);
    cudaGetSymbolAddress((void**)&ssrc, g_ssrc);

    cudaFuncSetAttribute(k_fused, cudaFuncAttributeMaxDynamicSharedMemorySize,
                         SMEM_FUSED);

    // ---- CSR build (by destination) ----
    k_zero2<<<(M + 255) / 256, 256>>>(cnt, fill, M);
    k_hist<<<(E + 255) / 256, 256>>>(edst, cnt, E);
    k_scan<<<1, 1024>>>(cnt, rp, M);
    k_scatter<<<(E + 255) / 256, 256>>>(esrc, edst, ew, rp, fill, ssrc, sw, E);

    int grid = (M + BM - 1) / BM;

    float* out_feats = (out_size >= M * 3 + M * H) ? (out + (size_t)M * 3) : nullptr;

    // layer 0: x = relu(gcn(features))
    k_fused<<<grid, 256, SMEM_FUSED>>>(features, rp, ssrc, sw, Ws, bs,
                                       features, X, nullptr, M, 0);
    // layer 1: feats = (features + relu(gcn(x))) / 2
    k_fused<<<grid, 256, SMEM_FUSED>>>(X, rp, ssrc, sw,
                                       Ws + (size_t)1 * H * H, bs + 1 * H,
                                       features, F, nullptr, M, 1);
    // blocks: layers (2,3) (4,5) (6,7) (8,9) (10,11)
    for (int l = 2; l < 12; l += 2) {
        k_fused<<<grid, 256, SMEM_FUSED>>>(F, rp, ssrc, sw,
                                           Ws + (size_t)l * H * H, bs + (size_t)l * H,
                                           F, X, nullptr, M, 0);
        k_fused<<<grid, 256, SMEM_FUSED>>>(X, rp, ssrc, sw,
                                           Ws + (size_t)(l + 1) * H * H,
                                           bs + (size_t)(l + 1) * H,
                                           F, F, nullptr, M, 1);
    }
    // gc13: feats = (feats + relu(gcn(feats))) / 2 ; dual-store into out feats region
    k_fused<<<grid, 256, SMEM_FUSED>>>(F, rp, ssrc, sw,
                                       Ws + (size_t)12 * H * H, bs + (size_t)12 * H,
                                       F, F, out_feats, M, 1);

    // head: coords = gcn(feats) with W_out/b_out (no relu)
    k_agg_head<<<(M * 32 + 255) / 256, 256>>>(F, rp, ssrc, sw, Wout, bout, out, M);
}

// round 13
// speedup vs baseline: 1.0299x; 1.0299x over previous
#include <cuda_runtime.h>
#include <cuda_fp16.h>
#include <cstddef>

#define NV 25000
#define NE 400000
#define H  192
#define BM 64
#define SCALE_UP 1024.0f
#define SCALE_DN (1.0f / 1024.0f)

// ---------------- scratch (static device globals; no runtime allocation) ---------
__device__ float  g_Y[(size_t)NV * H];    // aggregation output (fp32)
__device__ float  g_X[(size_t)NV * H];    // intra-block activation (fp32)
__device__ float  g_F[(size_t)NV * H];    // feats residual stream (fp32)
__device__ __half g_FEh[(size_t)NV * H];  // fp16 mirror of features  (x * 2^-10)
__device__ __half g_Xh[(size_t)NV * H];   // fp16 mirror of X         (x * 2^-10)
__device__ __half g_Fh[(size_t)NV * H];   // fp16 mirror of F         (x * 2^-10)
__device__ int    g_rowptr[NV + 1];
__device__ int    g_cnt[NV];
__device__ int    g_fill[NV];
__device__ int    g_ssrc[NE];
__device__ float  g_sw[NE];

// ---------------- CSR build ------------------------------------------------------
__global__ void k_zero2(int* a, int* b, int n) {
    int i = blockIdx.x * blockDim.x + threadIdx.x;
    if (i < n) { a[i] = 0; b[i] = 0; }
}

__global__ void k_hist(const int* __restrict__ dst, int* cnt, int E) {
    int i = blockIdx.x * blockDim.x + threadIdx.x;
    if (i < E) atomicAdd(&cnt[dst[i]], 1);
}

__global__ void k_scan(const int* __restrict__ cnt, int* __restrict__ rowptr, int n) {
    __shared__ int sh[1024];
    __shared__ int s_carry;
    if (threadIdx.x == 0) s_carry = 0;
    __syncthreads();
    for (int base = 0; base < n; base += 1024) {
        int i = base + threadIdx.x;
        int v = (i < n) ? cnt[i] : 0;
        int x = v;
        sh[threadIdx.x] = x;
        __syncthreads();
        for (int off = 1; off < 1024; off <<= 1) {
            int t = (threadIdx.x >= off) ? sh[threadIdx.x - off] : 0;
            __syncthreads();
            x += t;
            sh[threadIdx.x] = x;
            __syncthreads();
        }
        int carry = s_carry;
        if (i < n) rowptr[i] = carry + x - v;
        __syncthreads();
        if (threadIdx.x == 1023) s_carry = carry + sh[1023];
        __syncthreads();
    }
    if (threadIdx.x == 0) rowptr[n] = s_carry;
}

__global__ void k_scatter(const int* __restrict__ src, const int* __restrict__ dst,
                          const float* __restrict__ w, const int* __restrict__ rowptr,
                          int* fill, int* ssrc, float* sw, int E) {
    int i = blockIdx.x * blockDim.x + threadIdx.x;
    if (i < E) {
        int d = dst[i];
        int pos = rowptr[d] + atomicAdd(&fill[d], 1);
        ssrc[pos] = src[i];
        sw[pos]   = w[i];
    }
}

// ---------------- fp32 -> fp16*2^-10 convert (features mirror) -------------------
__global__ void k_cvt_h(const float* __restrict__ src, __half* __restrict__ dst, int n2) {
    int i = blockIdx.x * blockDim.x + threadIdx.x;
    if (i < n2) {
        float2 v = ((const float2*)src)[i];
        ((__half2*)dst)[i] = __floats2half2_rn(v.x * SCALE_DN, v.y * SCALE_DN);
    }
}

// ---------------- sparse aggregation: Y[d] = 2^10 * sum_e w_e * Xh[src_e] --------
// one warp per destination vertex. fp16 gather (384 B/edge), fp32 accumulate.
__global__ __launch_bounds__(256) void k_agg(const __half* __restrict__ Xh,
                                             float* __restrict__ Y,
                                             const int* __restrict__ rowptr,
                                             const int* __restrict__ ssrc,
                                             const float* __restrict__ sw, int M) {
    int warp = (blockIdx.x * blockDim.x + threadIdx.x) >> 5;
    int lane = threadIdx.x & 31;
    if (warp >= M) return;
    int beg = rowptr[warp], end = rowptr[warp + 1];
    float4 a4 = make_float4(0.f, 0.f, 0.f, 0.f);
    float2 a2 = make_float2(0.f, 0.f);
#pragma unroll 4
    for (int e = beg; e < end; e++) {
        int   s  = __ldg(ssrc + e);
        float wt = __ldg(sw + e);
        const __half* r = Xh + (size_t)s * H;
        uint2 u = __ldg((const uint2*)r + lane);              // halves lane*4 .. +3
        unsigned v = __ldg((const unsigned*)(r + 128) + lane); // halves 128+lane*2 .. +1
        float2 f0 = __half22float2(*(const __half2*)&u.x);
        float2 f1 = __half22float2(*(const __half2*)&u.y);
        float2 f2 = __half22float2(*(const __half2*)&v);
        a4.x += wt * f0.x;
        a4.y += wt * f0.y;
        a4.z += wt * f1.x;
        a4.w += wt * f1.y;
        a2.x += wt * f2.x;
        a2.y += wt * f2.y;
    }
    a4.x *= SCALE_UP; a4.y *= SCALE_UP; a4.z *= SCALE_UP; a4.w *= SCALE_UP;
    a2.x *= SCALE_UP; a2.y *= SCALE_UP;
    float* o = Y + (size_t)warp * H;
    ((float4*)o)[lane] = a4;
    ((float2*)(o + 128))[lane] = a2;
}

// ---------------- tf32 tensor-core GEMM + fused epilogue -------------------------
// C = A[M,192] @ W[192,192];  out = relu(C + bias)                (mode 0)
//                             out = (res + relu(C + bias)) * 0.5  (mode 1)
// writes fp32 out, scaled fp16 mirror outh, optional second fp32 out2.
#define SA 36
#define SB 200

__device__ __forceinline__ unsigned f2tf32(float x) {
    unsigned u;
    asm("cvt.rna.tf32.f32 %0, %1;" : "=r"(u) : "f"(x));
    return u;
}

__device__ __forceinline__ void mma_tf32(float* c, const unsigned* a,
                                         unsigned b0, unsigned b1) {
    asm volatile(
        "mma.sync.aligned.m16n8k8.row.col.f32.tf32.tf32.f32 "
        "{%0,%1,%2,%3}, {%4,%5,%6,%7}, {%8,%9}, {%0,%1,%2,%3};"
        : "+f"(c[0]), "+f"(c[1]), "+f"(c[2]), "+f"(c[3])
        : "r"(a[0]), "r"(a[1]), "r"(a[2]), "r"(a[3]), "r"(b0), "r"(b1));
}

__global__ __launch_bounds__(256) void k_gemm_tf32(const float* __restrict__ A,
                                                   const float* __restrict__ Wm,
                                                   const float* __restrict__ bias,
                                                   const float* __restrict__ res,
                                                   float* __restrict__ out,
                                                   __half* __restrict__ outh,
                                                   float* __restrict__ out2,
                                                   int M, int mode) {
    __shared__ unsigned As[BM * SA];
    __shared__ unsigned Bs[32 * SB];

    int tid  = threadIdx.x;
    int lane = tid & 31;
    int warp = tid >> 5;
    int gid  = lane >> 2;
    int tig  = lane & 3;
    int rowg = warp & 1;
    int colg = warp >> 1;
    int m0   = blockIdx.x * BM;

    float c[2][6][4];
#pragma unroll
    for (int t = 0; t < 2; t++)
#pragma unroll
        for (int j = 0; j < 6; j++)
#pragma unroll
            for (int q = 0; q < 4; q++) c[t][j][q] = 0.f;

    int arow = tid >> 2;
    int akk  = (tid & 3) * 8;

    for (int it = 0; it < 6; it++) {
        int k0 = it * 32;
        __syncthreads();
        {
            int gr = m0 + arow;
            float4 v0 = make_float4(0.f, 0.f, 0.f, 0.f);
            float4 v1 = v0;
            if (gr < M) {
                const float* p = A + (size_t)gr * H + k0 + akk;
                v0 = *(const float4*)p;
                v1 = *(const float4*)(p + 4);
            }
            unsigned* d = &As[arow * SA + akk];
            d[0] = f2tf32(v0.x); d[1] = f2tf32(v0.y);
            d[2] = f2tf32(v0.z); d[3] = f2tf32(v0.w);
            d[4] = f2tf32(v1.x); d[5] = f2tf32(v1.y);
            d[6] = f2tf32(v1.z); d[7] = f2tf32(v1.w);
        }
#pragma unroll
        for (int i = 0; i < 6; i++) {
            int f4  = tid + 256 * i;
            int row = f4 / 48;
            int cc  = (f4 % 48) * 4;
            float4 w = *(const float4*)(Wm + (size_t)(k0 + row) * H + cc);
            unsigned* d = &Bs[row * SB + cc];
            d[0] = f2tf32(w.x); d[1] = f2tf32(w.y);
            d[2] = f2tf32(w.z); d[3] = f2tf32(w.w);
        }
        __syncthreads();
#pragma unroll
        for (int ks = 0; ks < 4; ks++) {
            int kk = ks * 8;
            unsigned a[2][4];
#pragma unroll
            for (int t = 0; t < 2; t++) {
                int r = rowg * 32 + t * 16 + gid;
                a[t][0] = As[r * SA + kk + tig];
                a[t][1] = As[(r + 8) * SA + kk + tig];
                a[t][2] = As[r * SA + kk + tig + 4];
                a[t][3] = As[(r + 8) * SA + kk + tig + 4];
            }
#pragma unroll
            for (int j = 0; j < 6; j++) {
                int n = colg * 48 + j * 8 + gid;
                unsigned b0 = Bs[(kk + tig) * SB + n];
                unsigned b1 = Bs[(kk + tig + 4) * SB + n];
                mma_tf32(c[0][j], a[0], b0, b1);
                mma_tf32(c[1][j], a[1], b0, b1);
            }
        }
    }

    float2 bb[6];
#pragma unroll
    for (int j = 0; j < 6; j++)
        bb[j] = *(const float2*)(bias + colg * 48 + j * 8 + tig * 2);

#pragma unroll
    for (int t = 0; t < 2; t++) {
#pragma unroll
        for (int h = 0; h < 2; h++) {
            int m = m0 + rowg * 32 + t * 16 + gid + h * 8;
            if (m < M) {
                size_t off = (size_t)m * H + colg * 48 + tig * 2;
                const float* rrow = res + off;
#pragma unroll
                for (int j = 0; j < 6; j++) {
                    float v0 = fmaxf(c[t][j][h * 2 + 0] + bb[j].x, 0.f);
                    float v1 = fmaxf(c[t][j][h * 2 + 1] + bb[j].y, 0.f);
                    if (mode == 1) {
                        float2 r2 = *(const float2*)(rrow + j * 8);
                        v0 = (r2.x + v0) * 0.5f;
                        v1 = (r2.y + v1) * 0.5f;
                    }
                    float2 o2; o2.x = v0; o2.y = v1;
                    *(float2*)(out + off + j * 8) = o2;
                    *(__half2*)(outh + off + j * 8) =
                        __floats2half2_rn(v0 * SCALE_DN, v1 * SCALE_DN);
                    if (out2) *(float2*)(out2 + off + j * 8) = o2;
                }
            }
        }
    }
}

// ---------------- fused output head: coords = agg(Fh)*2^10 @ W_out + b_out -------
__global__ __launch_bounds__(256) void k_agg_head(const __half* __restrict__ Xh,
                                                  const int* __restrict__ rowptr,
                                                  const int* __restrict__ ssrc,
                                                  const float* __restrict__ sw,
                                                  const float* __restrict__ Wout,
                                                  const float* __restrict__ bout,
                                                  float* __restrict__ out, int M) {
    int warp = (blockIdx.x * blockDim.x + threadIdx.x) >> 5;
    int lane = threadIdx.x & 31;
    if (warp >= M) return;
    int beg = rowptr[warp], end = rowptr[warp + 1];
    float4 a4 = make_float4(0.f, 0.f, 0.f, 0.f);
    float2 a2 = make_float2(0.f, 0.f);
#pragma unroll 4
    for (int e = beg; e < end; e++) {
        int   s  = __ldg(ssrc + e);
        float wt = __ldg(sw + e);
        const __half* r = Xh + (size_t)s * H;
        uint2 u = __ldg((const uint2*)r + lane);
        unsigned v = __ldg((const unsigned*)(r + 128) + lane);
        float2 f0 = __half22float2(*(const __half2*)&u.x);
        float2 f1 = __half22float2(*(const __half2*)&u.y);
        float2 f2 = __half22float2(*(const __half2*)&v);
        a4.x += wt * f0.x;
        a4.y += wt * f0.y;
        a4.z += wt * f1.x;
        a4.w += wt * f1.y;
        a2.x += wt * f2.x;
        a2.y += wt * f2.y;
    }
    int c0 = lane * 4;
    int c1 = 128 + lane * 2;
    float s0 = 0.f, s1 = 0.f, s2 = 0.f;
    float av[6] = {a4.x, a4.y, a4.z, a4.w, a2.x, a2.y};
    int   cv[6] = {c0, c0 + 1, c0 + 2, c0 + 3, c1, c1 + 1};
#pragma unroll
    for (int q = 0; q < 6; q++) {
        const float* wr = Wout + (size_t)cv[q] * 3;
        s0 += av[q] * __ldg(wr + 0);
        s1 += av[q] * __ldg(wr + 1);
        s2 += av[q] * __ldg(wr + 2);
    }
#pragma unroll
    for (int off = 16; off; off >>= 1) {
        s0 += __shfl_down_sync(0xffffffffu, s0, off);
        s1 += __shfl_down_sync(0xffffffffu, s1, off);
        s2 += __shfl_down_sync(0xffffffffu, s2, off);
    }
    if (lane == 0) {
        out[(size_t)warp * 3 + 0] = s0 * SCALE_UP + __ldg(bout + 0);
        out[(size_t)warp * 3 + 1] = s1 * SCALE_UP + __ldg(bout + 1);
        out[(size_t)warp * 3 + 2] = s2 * SCALE_UP + __ldg(bout + 2);
    }
}

// ---------------- launch ---------------------------------------------------------
extern "C" void kernel_launch(void* const* d_in, const int* in_sizes, int n_in,
                              void* d_out, int out_size) {
    const float* features = (const float*)d_in[0];
    const int*   esrc     = (const int*)d_in[1];
    const int*   edst     = (const int*)d_in[2];
    const float* ew       = (const float*)d_in[3];
    const float* Ws       = (const float*)d_in[4];
    const float* bs       = (const float*)d_in[5];
    const float* Wout     = (const float*)d_in[6];
    const float* bout     = (const float*)d_in[7];
    float* out = (float*)d_out;

    int M = in_sizes[0] / H;   // 25000
    int E = in_sizes[1];       // 400000

    float *Y, *X, *F, *sw;
    __half *FEh, *Xh, *Fh;
    int *rp, *cnt, *fill, *ssrc;
    cudaGetSymbolAddress((void**)&Y, g_Y);
    cudaGetSymbolAddress((void**)&X, g_X);
    cudaGetSymbolAddress((void**)&F, g_F);
    cudaGetSymbolAddress((void**)&FEh, g_FEh);
    cudaGetSymbolAddress((void**)&Xh, g_Xh);
    cudaGetSymbolAddress((void**)&Fh, g_Fh);
    cudaGetSymbolAddress((void**)&sw, g_sw);
    cudaGetSymbolAddress((void**)&rp, g_rowptr);
    cudaGetSymbolAddress((void**)&cnt, g_cnt);
    cudaGetSymbolAddress((void**)&fill, g_fill);
    cudaGetSymbolAddress((void**)&ssrc, g_ssrc);

    // ---- CSR build (by destination) + scaled fp16 feature mirror ----
    k_zero2<<<(M + 255) / 256, 256>>>(cnt, fill, M);
    k_hist<<<(E + 255) / 256, 256>>>(edst, cnt, E);
    k_cvt_h<<<((M * H / 2) + 255) / 256, 256>>>(features, FEh, M * H / 2);
    k_scan<<<1, 1024>>>(cnt, rp, M);
    k_scatter<<<(E + 255) / 256, 256>>>(esrc, edst, ew, rp, fill, ssrc, sw, E);

    int aggGrid  = (M * 32 + 255) / 256;
    int gemmGrid = (M + BM - 1) / BM;
    float* out_feats = (out_size >= M * 3 + M * H) ? (out + (size_t)M * 3) : nullptr;

    // layer 0: x = relu(gcn(features))
    k_agg<<<aggGrid, 256>>>(FEh, Y, rp, ssrc, sw, M);
    k_gemm_tf32<<<gemmGrid, 256>>>(Y, Ws, bs, features /*unused*/, X, Xh, nullptr, M, 0);
    // layer 1: feats = (features + relu(gcn(x))) / 2
    k_agg<<<aggGrid, 256>>>(Xh, Y, rp, ssrc, sw, M);
    k_gemm_tf32<<<gemmGrid, 256>>>(Y, Ws + (size_t)1 * H * H, bs + 1 * H,
                                   features, F, Fh, nullptr, M, 1);

    // blocks: layers (2,3) (4,5) (6,7) (8,9) (10,11)
    for (int l = 2; l < 12; l += 2) {
        k_agg<<<aggGrid, 256>>>(Fh, Y, rp, ssrc, sw, M);
        k_gemm_tf32<<<gemmGrid, 256>>>(Y, Ws + (size_t)l * H * H, bs + (size_t)l * H,
                                       F /*unused*/, X, Xh, nullptr, M, 0);
        k_agg<<<aggGrid, 256>>>(Xh, Y, rp, ssrc, sw, M);
        k_gemm_tf32<<<gemmGrid, 256>>>(Y, Ws + (size_t)(l + 1) * H * H,
                                       bs + (size_t)(l + 1) * H,
                                       F, F, Fh, nullptr, M, 1);
    }

    // gc13: feats = (feats + relu(gcn(feats))) / 2 ; dual-store into out feats region
    k_agg<<<aggGrid, 256>>>(Fh, Y, rp, ssrc, sw, M);
    k_gemm_tf32<<<gemmGrid, 256>>>(Y, Ws + (size_t)12 * H * H, bs + (size_t)12 * H,
                                   F, F, Fh, out_feats, M, 1);

    // head: coords = gcn(feats) with W_out/b_out (no relu)
    k_agg_head<<<(M * 32 + 255) / 256, 256>>>(Fh, rp, ssrc, sw, Wout, bout, out, M);
}

// round 14
// speedup vs baseline: 1.1091x; 1.0769x over previous
#include <cuda_runtime.h>
#include <cstddef>

#define NV 25000
#define NE 400000
#define H  192
#define BM 64

// ---------------- scratch (static device globals; no runtime allocation) ---------
__device__ float g_Y[(size_t)NV * H];   // aggregation output
__device__ float g_X[(size_t)NV * H];   // intra-block activation
__device__ float g_F[(size_t)NV * H];   // feats (residual stream)
__device__ int   g_rowptr[NV + 1];
__device__ int   g_cnt[NV];
__device__ int   g_fill[NV];
__device__ int2  g_edge[NE];            // packed (src, weight-bits)
__device__ int   g_part[32];            // scan partials

// ---------------- CSR build ------------------------------------------------------
__global__ void k_zero2(int* a, int* b, int n) {
    int i = blockIdx.x * blockDim.x + threadIdx.x;
    if (i < n) { a[i] = 0; b[i] = 0; }
}

__global__ void k_hist(const int* __restrict__ dst, int* cnt, int E) {
    int i = blockIdx.x * blockDim.x + threadIdx.x;
    if (i < E) atomicAdd(&cnt[dst[i]], 1);
}

// hierarchical scan, stage 1: per-block exclusive scan + block totals
__global__ __launch_bounds__(1024) void k_scan_blk(const int* __restrict__ cnt,
                                                   int* __restrict__ rowptr,
                                                   int* __restrict__ partial, int n) {
    __shared__ int wsum[32];
    int i    = blockIdx.x * 1024 + threadIdx.x;
    int lane = threadIdx.x & 31;
    int w    = threadIdx.x >> 5;
    int v = (i < n) ? cnt[i] : 0;
    int x = v;
#pragma unroll
    for (int off = 1; off < 32; off <<= 1) {
        int t = __shfl_up_sync(0xffffffffu, x, off);
        if (lane >= off) x += t;
    }
    if (lane == 31) wsum[w] = x;
    __syncthreads();
    if (w == 0) {
        int s = wsum[lane];
#pragma unroll
        for (int off = 1; off < 32; off <<= 1) {
            int t = __shfl_up_sync(0xffffffffu, s, off);
            if (lane >= off) s += t;
        }
        wsum[lane] = s;
    }
    __syncthreads();
    int incl = x + (w > 0 ? wsum[w - 1] : 0);
    if (i < n) rowptr[i] = incl - v;          // block-local exclusive
    if (threadIdx.x == 1023) partial[blockIdx.x] = incl;  // block total
}

// stage 2: exclusive scan of <=32 block totals (single warp)
__global__ void k_scan_part(int* partial, int nb) {
    int lane = threadIdx.x;
    int v = (lane < nb) ? partial[lane] : 0;
    int x = v;
#pragma unroll
    for (int off = 1; off < 32; off <<= 1) {
        int t = __shfl_up_sync(0xffffffffu, x, off);
        if (lane >= off) x += t;
    }
    if (lane < nb) partial[lane] = x - v;
}

// stage 3: add block offsets; rowptr[n] = E
__global__ __launch_bounds__(1024) void k_scan_add(int* __restrict__ rowptr,
                                                   const int* __restrict__ partial,
                                                   int n, int E) {
    int i = blockIdx.x * 1024 + threadIdx.x;
    if (i < n) rowptr[i] += partial[blockIdx.x];
    if (i == 0) rowptr[n] = E;
}

__global__ void k_scatter(const int* __restrict__ src, const int* __restrict__ dst,
                          const float* __restrict__ w, const int* __restrict__ rowptr,
                          int* fill, int2* edge, int E) {
    int i = blockIdx.x * blockDim.x + threadIdx.x;
    if (i < E) {
        int d = dst[i];
        int pos = rowptr[d] + atomicAdd(&fill[d], 1);
        edge[pos] = make_int2(src[i], __float_as_int(w[i]));
    }
}

// ---------------- sparse aggregation: Y[d] = sum_e w_e * X[src_e] ----------------
// one warp per destination vertex; lane covers cols {lane*4..+3, 128+lane*2..+1}.
__global__ __launch_bounds__(256) void k_agg(const float* __restrict__ X,
                                             float* __restrict__ Y,
                                             const int* __restrict__ rowptr,
                                             const int2* __restrict__ edge, int M) {
    int warp = (blockIdx.x * blockDim.x + threadIdx.x) >> 5;
    int lane = threadIdx.x & 31;
    if (warp >= M) return;
    int beg = rowptr[warp], end = rowptr[warp + 1];
    float4 a4 = make_float4(0.f, 0.f, 0.f, 0.f);
    float2 a2 = make_float2(0.f, 0.f);
#pragma unroll 4
    for (int e = beg; e < end; e++) {
        int2  ed = __ldg(edge + e);
        int   s  = ed.x;
        float wt = __int_as_float(ed.y);
        const float* r = X + (size_t)s * H;
        float4 v4 = __ldg((const float4*)r + lane);
        float2 v2 = __ldg((const float2*)(r + 128) + lane);
        a4.x += wt * v4.x;
        a4.y += wt * v4.y;
        a4.z += wt * v4.z;
        a4.w += wt * v4.w;
        a2.x += wt * v2.x;
        a2.y += wt * v2.y;
    }
    float* o = Y + (size_t)warp * H;
    ((float4*)o)[lane] = a4;
    ((float2*)(o + 128))[lane] = a2;
}

// ---------------- tf32 tensor-core GEMM + fused epilogue -------------------------
// C = A[M,192] @ W[192,192];  out = relu(C + bias)                (mode 0)
//                             out = (res + relu(C + bias)) * 0.5  (mode 1)
#define SA 36
#define SB 200

__device__ __forceinline__ unsigned f2tf32(float x) {
    unsigned u;
    asm("cvt.rna.tf32.f32 %0, %1;" : "=r"(u) : "f"(x));
    return u;
}

__device__ __forceinline__ void mma_tf32(float* c, const unsigned* a,
                                         unsigned b0, unsigned b1) {
    asm volatile(
        "mma.sync.aligned.m16n8k8.row.col.f32.tf32.tf32.f32 "
        "{%0,%1,%2,%3}, {%4,%5,%6,%7}, {%8,%9}, {%0,%1,%2,%3};"
        : "+f"(c[0]), "+f"(c[1]), "+f"(c[2]), "+f"(c[3])
        : "r"(a[0]), "r"(a[1]), "r"(a[2]), "r"(a[3]), "r"(b0), "r"(b1));
}

__global__ __launch_bounds__(256) void k_gemm_tf32(const float* __restrict__ A,
                                                   const float* __restrict__ Wm,
                                                   const float* __restrict__ bias,
                                                   const float* __restrict__ res,
                                                   float* __restrict__ out,
                                                   float* __restrict__ out2,
                                                   int M, int mode) {
    __shared__ unsigned As[BM * SA];
    __shared__ unsigned Bs[32 * SB];

    int tid  = threadIdx.x;
    int lane = tid & 31;
    int warp = tid >> 5;
    int gid  = lane >> 2;
    int tig  = lane & 3;
    int rowg = warp & 1;
    int colg = warp >> 1;
    int m0   = blockIdx.x * BM;

    float c[2][6][4];
#pragma unroll
    for (int t = 0; t < 2; t++)
#pragma unroll
        for (int j = 0; j < 6; j++)
#pragma unroll
            for (int q = 0; q < 4; q++) c[t][j][q] = 0.f;

    int arow = tid >> 2;
    int akk  = (tid & 3) * 8;

    for (int it = 0; it < 6; it++) {
        int k0 = it * 32;
        __syncthreads();
        {
            int gr = m0 + arow;
            float4 v0 = make_float4(0.f, 0.f, 0.f, 0.f);
            float4 v1 = v0;
            if (gr < M) {
                const float* p = A + (size_t)gr * H + k0 + akk;
                v0 = *(const float4*)p;
                v1 = *(const float4*)(p + 4);
            }
            unsigned* d = &As[arow * SA + akk];
            d[0] = f2tf32(v0.x); d[1] = f2tf32(v0.y);
            d[2] = f2tf32(v0.z); d[3] = f2tf32(v0.w);
            d[4] = f2tf32(v1.x); d[5] = f2tf32(v1.y);
            d[6] = f2tf32(v1.z); d[7] = f2tf32(v1.w);
        }
#pragma unroll
        for (int i = 0; i < 6; i++) {
            int f4  = tid + 256 * i;
            int row = f4 / 48;
            int cc  = (f4 % 48) * 4;
            float4 w = *(const float4*)(Wm + (size_t)(k0 + row) * H + cc);
            unsigned* d = &Bs[row * SB + cc];
            d[0] = f2tf32(w.x); d[1] = f2tf32(w.y);
            d[2] = f2tf32(w.z); d[3] = f2tf32(w.w);
        }
        __syncthreads();
#pragma unroll
        for (int ks = 0; ks < 4; ks++) {
            int kk = ks * 8;
            unsigned a[2][4];
#pragma unroll
            for (int t = 0; t < 2; t++) {
                int r = rowg * 32 + t * 16 + gid;
                a[t][0] = As[r * SA + kk + tig];
                a[t][1] = As[(r + 8) * SA + kk + tig];
                a[t][2] = As[r * SA + kk + tig + 4];
                a[t][3] = As[(r + 8) * SA + kk + tig + 4];
            }
#pragma unroll
            for (int j = 0; j < 6; j++) {
                int n = colg * 48 + j * 8 + gid;
                unsigned b0 = Bs[(kk + tig) * SB + n];
                unsigned b1 = Bs[(kk + tig + 4) * SB + n];
                mma_tf32(c[0][j], a[0], b0, b1);
                mma_tf32(c[1][j], a[1], b0, b1);
            }
        }
    }

    float2 bb[6];
#pragma unroll
    for (int j = 0; j < 6; j++)
        bb[j] = *(const float2*)(bias + colg * 48 + j * 8 + tig * 2);

#pragma unroll
    for (int t = 0; t < 2; t++) {
#pragma unroll
        for (int h = 0; h < 2; h++) {
            int m = m0 + rowg * 32 + t * 16 + gid + h * 8;
            if (m < M) {
                size_t off = (size_t)m * H + colg * 48 + tig * 2;
                const float* rrow = res + off;
#pragma unroll
                for (int j = 0; j < 6; j++) {
                    float v0 = fmaxf(c[t][j][h * 2 + 0] + bb[j].x, 0.f);
                    float v1 = fmaxf(c[t][j][h * 2 + 1] + bb[j].y, 0.f);
                    if (mode == 1) {
                        float2 r2 = *(const float2*)(rrow + j * 8);
                        v0 = (r2.x + v0) * 0.5f;
                        v1 = (r2.y + v1) * 0.5f;
                    }
                    float2 o2; o2.x = v0; o2.y = v1;
                    *(float2*)(out + off + j * 8) = o2;
                    if (out2) *(float2*)(out2 + off + j * 8) = o2;
                }
            }
        }
    }
}

// ---------------- fused output head: coords = agg(F) @ W_out + b_out -------------
__global__ __launch_bounds__(256) void k_agg_head(const float* __restrict__ X,
                                                  const int* __restrict__ rowptr,
                                                  const int2* __restrict__ edge,
                                                  const float* __restrict__ Wout,
                                                  const float* __restrict__ bout,
                                                  float* __restrict__ out, int M) {
    int warp = (blockIdx.x * blockDim.x + threadIdx.x) >> 5;
    int lane = threadIdx.x & 31;
    if (warp >= M) return;
    int beg = rowptr[warp], end = rowptr[warp + 1];
    float4 a4 = make_float4(0.f, 0.f, 0.f, 0.f);
    float2 a2 = make_float2(0.f, 0.f);
#pragma unroll 4
    for (int e = beg; e < end; e++) {
        int2  ed = __ldg(edge + e);
        int   s  = ed.x;
        float wt = __int_as_float(ed.y);
        const float* r = X + (size_t)s * H;
        float4 v4 = __ldg((const float4*)r + lane);
        float2 v2 = __ldg((const float2*)(r + 128) + lane);
        a4.x += wt * v4.x;
        a4.y += wt * v4.y;
        a4.z += wt * v4.z;
        a4.w += wt * v4.w;
        a2.x += wt * v2.x;
        a2.y += wt * v2.y;
    }
    int c0 = lane * 4;
    int c1 = 128 + lane * 2;
    float s0 = 0.f, s1 = 0.f, s2 = 0.f;
    float av[6] = {a4.x, a4.y, a4.z, a4.w, a2.x, a2.y};
    int   cv[6] = {c0, c0 + 1, c0 + 2, c0 + 3, c1, c1 + 1};
#pragma unroll
    for (int q = 0; q < 6; q++) {
        const float* wr = Wout + (size_t)cv[q] * 3;
        s0 += av[q] * __ldg(wr + 0);
        s1 += av[q] * __ldg(wr + 1);
        s2 += av[q] * __ldg(wr + 2);
    }
#pragma unroll
    for (int off = 16; off; off >>= 1) {
        s0 += __shfl_down_sync(0xffffffffu, s0, off);
        s1 += __shfl_down_sync(0xffffffffu, s1, off);
        s2 += __shfl_down_sync(0xffffffffu, s2, off);
    }
    if (lane == 0) {
        out[(size_t)warp * 3 + 0] = s0 + __ldg(bout + 0);
        out[(size_t)warp * 3 + 1] = s1 + __ldg(bout + 1);
        out[(size_t)warp * 3 + 2] = s2 + __ldg(bout + 2);
    }
}

// ---------------- launch ---------------------------------------------------------
extern "C" void kernel_launch(void* const* d_in, const int* in_sizes, int n_in,
                              void* d_out, int out_size) {
    const float* features = (const float*)d_in[0];
    const int*   esrc     = (const int*)d_in[1];
    const int*   edst     = (const int*)d_in[2];
    const float* ew       = (const float*)d_in[3];
    const float* Ws       = (const float*)d_in[4];
    const float* bs       = (const float*)d_in[5];
    const float* Wout     = (const float*)d_in[6];
    const float* bout     = (const float*)d_in[7];
    float* out = (float*)d_out;

    int M = in_sizes[0] / H;   // 25000
    int E = in_sizes[1];       // 400000

    float *Y, *X, *F;
    int *rp, *cnt, *fill, *part;
    int2* edge;
    cudaGetSymbolAddress((void**)&Y, g_Y);
    cudaGetSymbolAddress((void**)&X, g_X);
    cudaGetSymbolAddress((void**)&F, g_F);
    cudaGetSymbolAddress((void**)&rp, g_rowptr);
    cudaGetSymbolAddress((void**)&cnt, g_cnt);
    cudaGetSymbolAddress((void**)&fill, g_fill);
    cudaGetSymbolAddress((void**)&edge, g_edge);
    cudaGetSymbolAddress((void**)&part, g_part);

    // ---- CSR build (by destination) ----
    int nb = (M + 1023) / 1024;   // 25
    k_zero2<<<(M + 255) / 256, 256>>>(cnt, fill, M);
    k_hist<<<(E + 255) / 256, 256>>>(edst, cnt, E);
    k_scan_blk<<<nb, 1024>>>(cnt, rp, part, M);
    k_scan_part<<<1, 32>>>(part, nb);
    k_scan_add<<<nb, 1024>>>(rp, part, M, E);
    k_scatter<<<(E + 255) / 256, 256>>>(esrc, edst, ew, rp, fill, edge, E);

    int aggGrid  = (M * 32 + 255) / 256;
    int gemmGrid = (M + BM - 1) / BM;
    float* out_feats = (out_size >= M * 3 + M * H) ? (out + (size_t)M * 3) : nullptr;

    // layer 0: x = relu(gcn(features))
    k_agg<<<aggGrid, 256>>>(features, Y, rp, edge, M);
    k_gemm_tf32<<<gemmGrid, 256>>>(Y, Ws, bs, features /*unused*/, X, nullptr, M, 0);
    // layer 1: feats = (features + relu(gcn(x))) / 2
    k_agg<<<aggGrid, 256>>>(X, Y, rp, edge, M);
    k_gemm_tf32<<<gemmGrid, 256>>>(Y, Ws + (size_t)1 * H * H, bs + 1 * H,
                                   features, F, nullptr, M, 1);

    // blocks: layers (2,3) (4,5) (6,7) (8,9) (10,11)
    for (int l = 2; l < 12; l += 2) {
        k_agg<<<aggGrid, 256>>>(F, Y, rp, edge, M);
        k_gemm_tf32<<<gemmGrid, 256>>>(Y, Ws + (size_t)l * H * H, bs + (size_t)l * H,
                                       F /*unused*/, X, nullptr, M, 0);
        k_agg<<<aggGrid, 256>>>(X, Y, rp, edge, M);
        k_gemm_tf32<<<gemmGrid, 256>>>(Y, Ws + (size_t)(l + 1) * H * H,
                                       bs + (size_t)(l + 1) * H,
                                       F, F, nullptr, M, 1);
    }

    // gc13: feats = (feats + relu(gcn(feats))) / 2 ; dual-store into out feats region
    k_agg<<<aggGrid, 256>>>(F, Y, rp, edge, M);
    k_gemm_tf32<<<gemmGrid, 256>>>(Y, Ws + (size_t)12 * H * H, bs + (size_t)12 * H,
                                   F, F, out_feats, M, 1);

    // head: coords = gcn(feats) with W_out/b_out (no relu)
    k_agg_head<<<(M * 32 + 255) / 256, 256>>>(F, rp, edge, Wout, bout, out, M);
}